// round 9
// baseline (speedup 1.0000x reference)
#include <cuda_runtime.h>
#include <cstddef>
#include <cstdint>

#define BB   64
#define TT   512
#define DD   300
#define HH   128
#define G4   512
#define HD2  256
#define LL   9
#define MTOK (TT*BB)

// ---------------- device scratch ----------------
__device__ float g_xp  [ (size_t)MTOK * 1024 ];
__device__ float g_hbuf[ (size_t)MTOK * HD2  ];
__device__ float g_wt  [ 2*2*HH*G4 ];            // [layer][dir][k][g]
__device__ float g_em  [ (size_t)BB*TT*LL ];
__device__ float g_llh [ BB ];

// ---------------- intrinsics ----------------
__device__ __forceinline__ unsigned long long pack2(float lo, float hi) {
    unsigned long long r;
    asm("mov.b64 %0, {%1, %2};" : "=l"(r) : "f"(lo), "f"(hi));
    return r;
}
__device__ __forceinline__ float2 unpack2(unsigned long long v) {
    float2 f;
    asm("mov.b64 {%0, %1}, %2;" : "=f"(f.x), "=f"(f.y) : "l"(v));
    return f;
}
__device__ __forceinline__ unsigned long long ffma2(unsigned long long a,
                                                    unsigned long long b,
                                                    unsigned long long c) {
    unsigned long long d;
    asm("fma.rn.f32x2 %0, %1, %2, %3;" : "=l"(d) : "l"(a), "l"(b), "l"(c));
    return d;
}
__device__ __forceinline__ float tanh_ap(float x) {
    float y;
    asm("tanh.approx.f32 %0, %1;" : "=f"(y) : "f"(x));
    return y;
}
__device__ __forceinline__ float sig_ap(float x) {
    return fmaf(tanh_ap(0.5f * x), 0.5f, 0.5f);
}
__device__ __forceinline__ void mma_tf32(float* d, const uint32_t* a, uint32_t b0, uint32_t b1) {
    asm("mma.sync.aligned.m16n8k8.row.col.f32.tf32.tf32.f32 "
        "{%0,%1,%2,%3}, {%4,%5,%6,%7}, {%8,%9}, {%0,%1,%2,%3};"
        : "+f"(d[0]), "+f"(d[1]), "+f"(d[2]), "+f"(d[3])
        : "r"(a[0]), "r"(a[1]), "r"(a[2]), "r"(a[3]), "r"(b0), "r"(b1));
}
__device__ __forceinline__ uint32_t bf16x2_of(float lo, float hi) {
    uint32_t r;
    asm("cvt.rn.bf16x2.f32 %0, %1, %2;" : "=r"(r) : "f"(hi), "f"(lo));
    return r;
}
__device__ __forceinline__ unsigned long long bfexp(uint32_t b) {
    uint32_t lo = __byte_perm(b, 0, 0x1044);
    uint32_t hi = __byte_perm(b, 0, 0x3244);
    unsigned long long r;
    asm("mov.b64 %0, {%1, %2};" : "=l"(r) : "r"(lo), "r"(hi));
    return r;
}
__device__ __forceinline__ void cp16(uint32_t dst, const void* src, int srcbytes) {
    asm volatile("cp.async.ca.shared.global [%0], [%1], 16, %2;"
                 :: "r"(dst), "l"(src), "r"(srcbytes));
}
__device__ __forceinline__ void cp_commit() {
    asm volatile("cp.async.commit_group;");
}
template<int N>
__device__ __forceinline__ void cp_wait() {
    asm volatile("cp.async.wait_group %0;" :: "n"(N));
}

// ---------------- 0) W_hh -> k-major ----------------
__global__ void transpose_whh(const float* __restrict__ w0, const float* __restrict__ w1)
{
    int i = blockIdx.x * blockDim.x + threadIdx.x;
    if (i >= 2*2*HH*G4) return;
    int layer = i >> 17;
    int r     = i & 131071;
    int dirr  = r >> 16;
    int r2    = r & 65535;
    int k     = r2 >> 9;
    int g     = r2 & 511;
    const float* w = layer ? w1 : w0;
    g_wt[i] = w[dirr*65536 + g*HH + k];
}

// ---------------- 1) tf32 GEMM: cp.async 3-stage pipeline ----------------
#define GST 3
#define KT  16
#define GPITCH 20
#define GEMM_SMEM (GST*128*GPITCH*4*2)

template<bool GATHER>
__global__ void __launch_bounds__(256)
gemm_tf32(const float* __restrict__ Asrc, const int* __restrict__ word,
          const float* __restrict__ W, const float* __restrict__ b1,
          const float* __restrict__ b2, int K)
{
    extern __shared__ uint32_t dsm[];
    uint32_t* AsB = dsm;
    uint32_t* BsB = dsm + GST*128*GPITCH;

    __shared__ const float* arow_s[128];
    __shared__ float bias_s[128];

    const int tid = threadIdx.x;
    const int m0 = blockIdx.x * 128, n0 = blockIdx.y * 128;

    if (tid < 128) {
        int n = n0 + tid;
        bias_s[tid] = b1[n] + b2[n];
        int m = m0 + tid;
        const float* ap;
        if (GATHER) {
            int b = m & 63, t = m >> 6;
            ap = Asrc + (size_t)word[b*TT + t] * K;
        } else {
            ap = g_hbuf + (size_t)m * K;
        }
        arow_s[tid] = ap;
    }
    __syncthreads();

    const int r  = tid >> 2;
    const int kq = (tid & 3) * 4;
    const float* ar0 = arow_s[r];
    const float* ar1 = arow_s[r + 64];
    const float* br0 = W + (size_t)(n0 + r) * K;
    const float* br1 = W + (size_t)(n0 + r + 64) * K;

    uint32_t a_dst0 = (uint32_t)__cvta_generic_to_shared(AsB + (size_t)r        * GPITCH + kq);
    uint32_t a_dst1 = (uint32_t)__cvta_generic_to_shared(AsB + (size_t)(r + 64) * GPITCH + kq);
    uint32_t b_dst0 = (uint32_t)__cvta_generic_to_shared(BsB + (size_t)r        * GPITCH + kq);
    uint32_t b_dst1 = (uint32_t)__cvta_generic_to_shared(BsB + (size_t)(r + 64) * GPITCH + kq);
    const uint32_t stB = 128*GPITCH*4;

    const int warp  = tid >> 5;
    const int lane  = tid & 31;
    const int wm    = warp >> 1;
    const int wn    = warp & 1;
    const int group = lane >> 2;
    const int tig   = lane & 3;

    float acc[2][8][4];
#pragma unroll
    for (int mt = 0; mt < 2; mt++)
#pragma unroll
        for (int nt = 0; nt < 8; nt++)
#pragma unroll
            for (int q = 0; q < 4; q++) acc[mt][nt][q] = 0.f;

    const int NT = (K + KT - 1) / KT;

    auto issue_tile = [&](int kt) {
        int st = kt % GST;
        int k  = kt * KT + kq;
        int sz = (k + 4 <= K) ? 16 : 0;
        int kc = (k + 4 <= K) ? k : 0;
        cp16(a_dst0 + st*stB, ar0 + kc, sz);
        cp16(a_dst1 + st*stB, ar1 + kc, sz);
        cp16(b_dst0 + st*stB, br0 + kc, sz);
        cp16(b_dst1 + st*stB, br1 + kc, sz);
    };

    issue_tile(0); cp_commit();
    if (NT > 1) { issue_tile(1); cp_commit(); }
    else cp_commit();

    for (int kt = 0; kt < NT; kt++) {
        cp_wait<1>();
        __syncthreads();

        if (kt + 2 < NT) issue_tile(kt + 2);
        cp_commit();

        const uint32_t* Ast = AsB + (size_t)(kt % GST) * 128 * GPITCH;
        const uint32_t* Bst = BsB + (size_t)(kt % GST) * 128 * GPITCH;

#pragma unroll
        for (int hf = 0; hf < 2; hf++) {
            int ko = hf * 8;
            uint32_t afr[2][4];
#pragma unroll
            for (int mt = 0; mt < 2; mt++) {
                int mr = wm*32 + mt*16 + group;
                afr[mt][0] = Ast[(mr    )*GPITCH + ko + tig];
                afr[mt][1] = Ast[(mr + 8)*GPITCH + ko + tig];
                afr[mt][2] = Ast[(mr    )*GPITCH + ko + tig + 4];
                afr[mt][3] = Ast[(mr + 8)*GPITCH + ko + tig + 4];
            }
#pragma unroll
            for (int nt = 0; nt < 8; nt++) {
                int nc = wn*64 + nt*8 + group;
                uint32_t bv0 = Bst[nc*GPITCH + ko + tig];
                uint32_t bv1 = Bst[nc*GPITCH + ko + tig + 4];
                mma_tf32(acc[0][nt], afr[0], bv0, bv1);
                mma_tf32(acc[1][nt], afr[1], bv0, bv1);
            }
        }
        __syncthreads();
    }

#pragma unroll
    for (int mt = 0; mt < 2; mt++) {
        int row = m0 + wm*32 + mt*16 + group;
#pragma unroll
        for (int nt = 0; nt < 8; nt++) {
            int ncl = wn*64 + nt*8 + 2*tig;
            float bc0 = bias_s[ncl], bc1 = bias_s[ncl + 1];
            float* r0 = g_xp + (size_t)row * 1024 + n0 + ncl;
            float* r1 = r0 + (size_t)8 * 1024;
            r0[0] = acc[mt][nt][0] + bc0;  r0[1] = acc[mt][nt][1] + bc1;
            r1[0] = acc[mt][nt][2] + bc0;  r1[1] = acc[mt][nt][3] + bc1;
        }
    }
}

// ---------------- 2) LSTM scan: all weights in registers ----------------
// 128 CTAs = (dir, b), 512 threads; thread g owns gate g.
// k 0..79 as 40 f32x2 register pairs; k 80..127 as 24 bf16x2 registers.
#define NF32P 40
#define NBFP  24

__global__ void __launch_bounds__(512, 1)
lstm_scan(int layer)
{
    __shared__ __align__(16) float h_s[128];
    __shared__ float gex[512];

    const int g   = threadIdx.x;
    const int dir = blockIdx.x >> 6;
    const int b   = blockIdx.x & 63;
    const float* pw = g_wt + (size_t)(layer*2 + dir) * 65536;

    unsigned long long wf[NF32P];
#pragma unroll
    for (int p = 0; p < NF32P; p++)
        wf[p] = pack2(pw[(2*p)*512 + g], pw[(2*p+1)*512 + g]);

    uint32_t wb[NBFP];
#pragma unroll
    for (int p = 0; p < NBFP; p++) {
        int k = 80 + 2*p;
        wb[p] = bf16x2_of(pw[(size_t)k*512 + g], pw[(size_t)(k+1)*512 + g]);
    }

    if (g < 128) h_s[g] = 0.f;
    float c = 0.f;
    __syncthreads();

    const float* xpp = g_xp + (size_t)(dir*512 + g);
    int t0 = dir ? (TT - 1) : 0;
    float xcur = xpp[(size_t)(t0*64 + b) * 1024];

    for (int s = 0; s < TT; s++) {
        int t = dir ? (TT - 1 - s) : s;
        int m = t*64 + b;

        float xnext = 0.f;
        if (s + 1 < TT) {
            int tn = dir ? (t - 1) : (t + 1);
            xnext = __ldg(xpp + (size_t)(tn*64 + b) * 1024);
        }

        const ulonglong2* h22 = (const ulonglong2*)h_s;
        unsigned long long acc0 = pack2(xcur, 0.f);
        unsigned long long acc1 = pack2(0.f, 0.f);
#pragma unroll
        for (int q = 0; q < NF32P/2; q++) {          // k 0..79
            ulonglong2 hv = h22[q];
            acc0 = ffma2(hv.x, wf[2*q],     acc0);
            acc1 = ffma2(hv.y, wf[2*q + 1], acc1);
        }
#pragma unroll
        for (int q = 0; q < NBFP/2; q++) {           // k 80..127 (bf16 regs)
            ulonglong2 hv = h22[NF32P/2 + q];
            acc0 = ffma2(hv.x, bfexp(wb[2*q]),     acc0);
            acc1 = ffma2(hv.y, bfexp(wb[2*q + 1]), acc1);
        }
        float2 s0 = unpack2(acc0);
        float2 s1 = unpack2(acc1);
        gex[g] = (s0.x + s1.x) + (s0.y + s1.y);
        __syncthreads();

        if (g < 128) {
            float i_ = sig_ap(gex[g]);
            float f_ = sig_ap(gex[128 + g]);
            float gg = tanh_ap(gex[256 + g]);
            float o_ = sig_ap(gex[384 + g]);
            c = fmaf(f_, c, i_ * gg);
            float h = o_ * tanh_ap(c);
            h_s[g] = h;
            g_hbuf[(size_t)m * 256 + dir*128 + g] = h;
        }
        __syncthreads();
        xcur = xnext;
    }
}

// ---------------- 3) emission ----------------
__global__ void __launch_bounds__(256)
emission(const float* __restrict__ wout, const float* __restrict__ bout)
{
    __shared__ float ws[LL*256];
    __shared__ float bs[LL];
    int tid = threadIdx.x;
    for (int i = tid; i < LL*256; i += 256) ws[i] = wout[i];
    if (tid < LL) bs[tid] = bout[tid];
    __syncthreads();

    int w = tid >> 5, lane = tid & 31;
    int m = blockIdx.x * 8 + w;
    const float* xr = g_hbuf + (size_t)m * 256;

    float acc[LL];
#pragma unroll
    for (int l = 0; l < LL; l++) acc[l] = 0.f;
#pragma unroll
    for (int q = 0; q < 8; q++) {
        float xv = xr[lane + q*32];
#pragma unroll
        for (int l = 0; l < LL; l++) acc[l] = fmaf(xv, ws[l*256 + lane + q*32], acc[l]);
    }
#pragma unroll
    for (int l = 0; l < LL; l++)
#pragma unroll
        for (int o = 16; o > 0; o >>= 1)
            acc[l] += __shfl_xor_sync(0xffffffffu, acc[l], o);

    if (lane == 0) {
        int t = m >> 6, b = m & 63;
        float* e = g_em + (size_t)b * (TT*LL) + t*LL;
#pragma unroll
        for (int l = 0; l < LL; l++) e[l] = acc[l] + bs[l];
    }
}

// ---------------- 4) CRF ----------------
__global__ void __launch_bounds__(32)
crf_kernel(const int* __restrict__ word, const int* __restrict__ label,
           const float* __restrict__ start_t, const float* __restrict__ end_t,
           const float* __restrict__ trans)
{
    int b = blockIdx.x;
    int lane = threadIdx.x;
    const float* emb_ = g_em + (size_t)b * (TT*LL);

    float tr[LL];
#pragma unroll
    for (int i = 0; i < LL; i++) tr[i] = 0.f;
    if (lane < LL)
#pragma unroll
        for (int i = 0; i < LL; i++) tr[i] = trans[i*LL + lane];

    float alpha = -1e30f;
    if (lane < LL) alpha = start_t[lane] + emb_[lane];

    for (int t = 1; t < TT; t++) {
        bool mt = word[b*TT + t] > 0;
        float emj = (lane < LL) ? emb_[t*LL + lane] : 0.f;
        float vs[LL], mx = -1e30f;
#pragma unroll
        for (int i = 0; i < LL; i++) {
            float ai = __shfl_sync(0xffffffffu, alpha, i);
            vs[i] = ai + tr[i];
            mx = fmaxf(mx, vs[i]);
        }
        float s = 0.f;
#pragma unroll
        for (int i = 0; i < LL; i++) s += __expf(vs[i] - mx);
        float nxt = mx + __logf(s) + emj;
        if (lane < LL && mt) alpha = nxt;
    }

    float v = (lane < LL) ? alpha + end_t[lane] : -1e30f;
    float mx = v;
#pragma unroll
    for (int o = 16; o > 0; o >>= 1) mx = fmaxf(mx, __shfl_xor_sync(0xffffffffu, mx, o));
    float s = __expf(v - mx);
#pragma unroll
    for (int o = 16; o > 0; o >>= 1) s += __shfl_xor_sync(0xffffffffu, s, o);
    float denom = mx + __logf(s);

    float partial = 0.f;
    int cnt = 0;
    for (int t = lane; t < TT; t += 32) {
        int mt = word[b*TT + t] > 0;
        cnt += mt;
        if (t >= 1 && mt) {
            int tp = label[b*TT + t - 1];
            int tc = label[b*TT + t];
            partial += trans[tp*LL + tc] + emb_[t*LL + tc];
        }
    }
#pragma unroll
    for (int o = 16; o > 0; o >>= 1) {
        partial += __shfl_xor_sync(0xffffffffu, partial, o);
        cnt     += __shfl_xor_sync(0xffffffffu, cnt, o);
    }
    if (lane == 0) {
        int t0 = label[b*TT];
        float num = start_t[t0] + emb_[t0] + partial;
        int last = label[b*TT + cnt - 1];
        num += end_t[last];
        g_llh[b] = num - denom;
    }
}

// ---------------- 5) final reduce ----------------
__global__ void __launch_bounds__(32)
finalize(float* out)
{
    int lane = threadIdx.x;
    float v = g_llh[lane] + g_llh[lane + 32];
#pragma unroll
    for (int o = 16; o > 0; o >>= 1) v += __shfl_xor_sync(0xffffffffu, v, o);
    if (lane == 0) out[0] = -v;
}

// ---------------- host ----------------
extern "C" void kernel_launch(void* const* d_in, const int* in_sizes, int n_in,
                              void* d_out, int out_size)
{
    const int*   word    = (const int*)  d_in[0];
    const int*   label   = (const int*)  d_in[1];
    const float* emb     = (const float*)d_in[2];
    const float* w_ih_l0 = (const float*)d_in[3];
    const float* w_hh_l0 = (const float*)d_in[4];
    const float* b_ih_l0 = (const float*)d_in[5];
    const float* b_hh_l0 = (const float*)d_in[6];
    const float* w_ih_l1 = (const float*)d_in[7];
    const float* w_hh_l1 = (const float*)d_in[8];
    const float* b_ih_l1 = (const float*)d_in[9];
    const float* b_hh_l1 = (const float*)d_in[10];
    const float* w_out   = (const float*)d_in[11];
    const float* b_out   = (const float*)d_in[12];
    const float* start_t = (const float*)d_in[13];
    const float* end_t   = (const float*)d_in[14];
    const float* trans   = (const float*)d_in[15];
    float* out = (float*)d_out;

    cudaFuncSetAttribute(gemm_tf32<true>,  cudaFuncAttributeMaxDynamicSharedMemorySize, GEMM_SMEM);
    cudaFuncSetAttribute(gemm_tf32<false>, cudaFuncAttributeMaxDynamicSharedMemorySize, GEMM_SMEM);

    transpose_whh<<<512, 512>>>(w_hh_l0, w_hh_l1);

    gemm_tf32<true ><<<dim3(256, 8), 256, GEMM_SMEM>>>(emb, word, w_ih_l0, b_ih_l0, b_hh_l0, DD);
    lstm_scan<<<128, 512>>>(0);

    gemm_tf32<false><<<dim3(256, 8), 256, GEMM_SMEM>>>(nullptr, word, w_ih_l1, b_ih_l1, b_hh_l1, HD2);
    lstm_scan<<<128, 512>>>(1);

    emission<<<MTOK/8, 256>>>(w_out, b_out);
    crf_kernel<<<BB, 32>>>(word, label, start_t, end_t, trans);
    finalize<<<1, 32>>>(out);
}

// round 10
// speedup vs baseline: 1.2137x; 1.2137x over previous
#include <cuda_runtime.h>
#include <cstddef>
#include <cstdint>

#define BB   64
#define TT   512
#define DD   300
#define HH   128
#define G4   512
#define HD2  256
#define LL   9
#define MTOK (TT*BB)

// ---------------- device scratch ----------------
__device__ float g_xp  [ (size_t)MTOK * 1024 ];
__device__ float g_hbuf[ (size_t)MTOK * HD2  ];
__device__ float g_wt  [ 2*2*HH*G4 ];            // [layer][dir][k][g]
__device__ float g_em  [ (size_t)BB*TT*LL ];
__device__ float g_llh [ BB ];

// ---------------- intrinsics ----------------
__device__ __forceinline__ unsigned long long pack2(float lo, float hi) {
    unsigned long long r;
    asm("mov.b64 %0, {%1, %2};" : "=l"(r) : "f"(lo), "f"(hi));
    return r;
}
__device__ __forceinline__ float2 unpack2(unsigned long long v) {
    float2 f;
    asm("mov.b64 {%0, %1}, %2;" : "=f"(f.x), "=f"(f.y) : "l"(v));
    return f;
}
__device__ __forceinline__ unsigned long long ffma2(unsigned long long a,
                                                    unsigned long long b,
                                                    unsigned long long c) {
    unsigned long long d;
    asm("fma.rn.f32x2 %0, %1, %2, %3;" : "=l"(d) : "l"(a), "l"(b), "l"(c));
    return d;
}
__device__ __forceinline__ float tanh_ap(float x) {
    float y;
    asm("tanh.approx.f32 %0, %1;" : "=f"(y) : "f"(x));
    return y;
}
__device__ __forceinline__ float sig_ap(float x) {
    return fmaf(tanh_ap(0.5f * x), 0.5f, 0.5f);
}
__device__ __forceinline__ void mma_tf32(float* d, const uint32_t* a, uint32_t b0, uint32_t b1) {
    asm("mma.sync.aligned.m16n8k8.row.col.f32.tf32.tf32.f32 "
        "{%0,%1,%2,%3}, {%4,%5,%6,%7}, {%8,%9}, {%0,%1,%2,%3};"
        : "+f"(d[0]), "+f"(d[1]), "+f"(d[2]), "+f"(d[3])
        : "r"(a[0]), "r"(a[1]), "r"(a[2]), "r"(a[3]), "r"(b0), "r"(b1));
}
__device__ __forceinline__ uint32_t bf16x2_of(float lo, float hi) {
    uint32_t r;
    asm("cvt.rn.bf16x2.f32 %0, %1, %2;" : "=r"(r) : "f"(hi), "f"(lo));
    return r;
}
__device__ __forceinline__ unsigned long long bfexp(uint32_t b) {
    uint32_t lo = __byte_perm(b, 0, 0x1044);
    uint32_t hi = __byte_perm(b, 0, 0x3244);
    unsigned long long r;
    asm("mov.b64 %0, {%1, %2};" : "=l"(r) : "r"(lo), "r"(hi));
    return r;
}
__device__ __forceinline__ void cp16(uint32_t dst, const void* src, int srcbytes) {
    asm volatile("cp.async.ca.shared.global [%0], [%1], 16, %2;"
                 :: "r"(dst), "l"(src), "r"(srcbytes));
}
__device__ __forceinline__ void cp_commit() {
    asm volatile("cp.async.commit_group;");
}
template<int N>
__device__ __forceinline__ void cp_wait() {
    asm volatile("cp.async.wait_group %0;" :: "n"(N));
}

// ---------------- 0) W_hh -> k-major ----------------
__global__ void transpose_whh(const float* __restrict__ w0, const float* __restrict__ w1)
{
    int i = blockIdx.x * blockDim.x + threadIdx.x;
    if (i >= 2*2*HH*G4) return;
    int layer = i >> 17;
    int r     = i & 131071;
    int dirr  = r >> 16;
    int r2    = r & 65535;
    int k     = r2 >> 9;
    int g     = r2 & 511;
    const float* w = layer ? w1 : w0;
    g_wt[i] = w[dirr*65536 + g*HH + k];
}

// ---------------- 1) tf32 GEMM: cp.async 3-stage, k-tile 32 ----------------
#define GST 3
#define KT  32
#define GPITCH 36
#define GEMM_SMEM (GST*128*GPITCH*4*2)

template<bool GATHER>
__global__ void __launch_bounds__(256)
gemm_tf32(const float* __restrict__ Asrc, const int* __restrict__ word,
          const float* __restrict__ W, const float* __restrict__ b1,
          const float* __restrict__ b2, int K)
{
    extern __shared__ uint32_t dsm[];
    uint32_t* AsB = dsm;
    uint32_t* BsB = dsm + GST*128*GPITCH;

    __shared__ const float* arow_s[128];
    __shared__ float bias_s[128];

    const int tid = threadIdx.x;
    const int m0 = blockIdx.x * 128, n0 = blockIdx.y * 128;

    if (tid < 128) {
        int n = n0 + tid;
        bias_s[tid] = b1[n] + b2[n];
        int m = m0 + tid;
        const float* ap;
        if (GATHER) {
            int b = m & 63, t = m >> 6;
            ap = Asrc + (size_t)word[b*TT + t] * K;
        } else {
            ap = g_hbuf + (size_t)m * K;
        }
        arow_s[tid] = ap;
    }
    __syncthreads();

    // loaders: row r2 = tid>>1 (0..127), half ch = tid&1 (k offset 16*ch)
    const int r2 = tid >> 1;
    const int ch = tid & 1;
    const float* arow = arow_s[r2];
    const float* brow = W + (size_t)(n0 + r2) * K;

    uint32_t a_dst[4], b_dst[4];
#pragma unroll
    for (int j = 0; j < 4; j++) {
        int off = r2*GPITCH + ch*16 + j*4;
        a_dst[j] = (uint32_t)__cvta_generic_to_shared(AsB + off);
        b_dst[j] = (uint32_t)__cvta_generic_to_shared(BsB + off);
    }
    const uint32_t stB = 128*GPITCH*4;

    const int warp  = tid >> 5;
    const int lane  = tid & 31;
    const int wm    = warp >> 1;
    const int wn    = warp & 1;
    const int group = lane >> 2;
    const int tig   = lane & 3;

    float acc[2][8][4];
#pragma unroll
    for (int mt = 0; mt < 2; mt++)
#pragma unroll
        for (int nt = 0; nt < 8; nt++)
#pragma unroll
            for (int q = 0; q < 4; q++) acc[mt][nt][q] = 0.f;

    const int NT = (K + KT - 1) / KT;

    auto issue_tile = [&](int kt) {
        uint32_t so = (uint32_t)(kt % GST) * stB;
#pragma unroll
        for (int j = 0; j < 4; j++) {
            int k = kt*KT + ch*16 + j*4;
            int sz = (k + 4 <= K) ? 16 : 0;
            int kc = sz ? k : 0;
            cp16(a_dst[j] + so, arow + kc, sz);
            cp16(b_dst[j] + so, brow + kc, sz);
        }
    };

    issue_tile(0); cp_commit();
    if (NT > 1) { issue_tile(1); cp_commit(); }
    else cp_commit();

    for (int kt = 0; kt < NT; kt++) {
        cp_wait<1>();
        __syncthreads();

        if (kt + 2 < NT) issue_tile(kt + 2);
        cp_commit();

        const uint32_t* Ast = AsB + (size_t)(kt % GST) * 128 * GPITCH;
        const uint32_t* Bst = BsB + (size_t)(kt % GST) * 128 * GPITCH;

#pragma unroll
        for (int hf = 0; hf < 4; hf++) {
            int ko = hf * 8;
            uint32_t afr[2][4];
#pragma unroll
            for (int mt = 0; mt < 2; mt++) {
                int mr = wm*32 + mt*16 + group;
                afr[mt][0] = Ast[(mr    )*GPITCH + ko + tig];
                afr[mt][1] = Ast[(mr + 8)*GPITCH + ko + tig];
                afr[mt][2] = Ast[(mr    )*GPITCH + ko + tig + 4];
                afr[mt][3] = Ast[(mr + 8)*GPITCH + ko + tig + 4];
            }
#pragma unroll
            for (int nt = 0; nt < 8; nt++) {
                int nc = wn*64 + nt*8 + group;
                uint32_t bv0 = Bst[nc*GPITCH + ko + tig];
                uint32_t bv1 = Bst[nc*GPITCH + ko + tig + 4];
                mma_tf32(acc[0][nt], afr[0], bv0, bv1);
                mma_tf32(acc[1][nt], afr[1], bv0, bv1);
            }
        }
        __syncthreads();
    }

#pragma unroll
    for (int mt = 0; mt < 2; mt++) {
        int row = m0 + wm*32 + mt*16 + group;
#pragma unroll
        for (int nt = 0; nt < 8; nt++) {
            int ncl = wn*64 + nt*8 + 2*tig;
            float bc0 = bias_s[ncl], bc1 = bias_s[ncl + 1];
            float* r0 = g_xp + (size_t)row * 1024 + n0 + ncl;
            float* r1 = r0 + (size_t)8 * 1024;
            r0[0] = acc[mt][nt][0] + bc0;  r0[1] = acc[mt][nt][1] + bc1;
            r1[0] = acc[mt][nt][2] + bc0;  r1[1] = acc[mt][nt][3] + bc1;
        }
    }
}

// ---------------- 2) LSTM scan (R7 exact: 48 f32x2 regs + 8 uint2 bf16 smem) ----------------
#define NREGP 48
#define NSMB  8
#define SCAN_SMEM (NSMB*512*8 + 128*4 + 512*4)

__global__ void __launch_bounds__(512, 1)
lstm_scan(int layer)
{
    extern __shared__ float sm[];
    uint2* wsb = (uint2*)sm;
    float* h_s = (float*)(wsb + NSMB*512);
    float* gex = h_s + 128;

    const int g   = threadIdx.x;
    const int dir = blockIdx.x >> 6;
    const int b   = blockIdx.x & 63;
    const float* pw = g_wt + (size_t)(layer*2 + dir) * 65536;

    unsigned long long wreg[NREGP];
#pragma unroll
    for (int p = 0; p < NREGP; p++)
        wreg[p] = pack2(pw[(2*p)*512 + g], pw[(2*p+1)*512 + g]);

    for (int j = 0; j < NSMB; j++) {
        int kb = 96 + 4*j;
        uint2 v;
        v.x = bf16x2_of(pw[(kb  )*512 + g], pw[(kb+1)*512 + g]);
        v.y = bf16x2_of(pw[(kb+2)*512 + g], pw[(kb+3)*512 + g]);
        wsb[j*512 + g] = v;
    }

    if (g < 128) h_s[g] = 0.f;
    float c = 0.f;
    __syncthreads();

    const float* xpp = g_xp + (size_t)(dir*512 + g);
    int t0 = dir ? (TT - 1) : 0;
    float xcur = xpp[(size_t)(t0*64 + b) * 1024];

    for (int s = 0; s < TT; s++) {
        int t = dir ? (TT - 1 - s) : s;
        int m = t*64 + b;

        float xnext = 0.f;
        if (s + 1 < TT) {
            int tn = dir ? (t - 1) : (t + 1);
            xnext = __ldg(xpp + (size_t)(tn*64 + b) * 1024);
        }

        const ulonglong2* h22 = (const ulonglong2*)h_s;
        unsigned long long acc0 = pack2(xcur, 0.f);
        unsigned long long acc1 = pack2(0.f, 0.f);
#pragma unroll
        for (int j = 0; j < NREGP/2; j++) {
            ulonglong2 hv = h22[j];
            acc0 = ffma2(hv.x, wreg[2*j],     acc0);
            acc1 = ffma2(hv.y, wreg[2*j + 1], acc1);
        }
#pragma unroll
        for (int j = 0; j < NSMB; j++) {
            ulonglong2 hv = h22[NREGP/2 + j];
            uint2 wb = wsb[j*512 + g];
            acc0 = ffma2(hv.x, bfexp(wb.x), acc0);
            acc1 = ffma2(hv.y, bfexp(wb.y), acc1);
        }
        float2 s0 = unpack2(acc0);
        float2 s1 = unpack2(acc1);
        gex[g] = (s0.x + s1.x) + (s0.y + s1.y);
        __syncthreads();

        if (g < 128) {
            float i_ = sig_ap(gex[g]);
            float f_ = sig_ap(gex[128 + g]);
            float gg = tanh_ap(gex[256 + g]);
            float o_ = sig_ap(gex[384 + g]);
            c = fmaf(f_, c, i_ * gg);
            float h = o_ * tanh_ap(c);
            h_s[g] = h;
            g_hbuf[(size_t)m * 256 + dir*128 + g] = h;
        }
        __syncthreads();
        xcur = xnext;
    }
}

// ---------------- 3) emission: 4 tokens per warp ----------------
__global__ void __launch_bounds__(256)
emission(const float* __restrict__ wout, const float* __restrict__ bout)
{
    __shared__ float ws[LL*256];
    __shared__ float bs[LL];
    int tid = threadIdx.x;
    for (int i = tid; i < LL*256; i += 256) ws[i] = wout[i];
    if (tid < LL) bs[tid] = bout[tid];
    __syncthreads();

    int w = tid >> 5, lane = tid & 31;

    for (int q4 = 0; q4 < 4; q4++) {
        int m = blockIdx.x * 32 + w * 4 + q4;
        const float* xr = g_hbuf + (size_t)m * 256;

        float acc[LL];
#pragma unroll
        for (int l = 0; l < LL; l++) acc[l] = 0.f;
#pragma unroll
        for (int q = 0; q < 8; q++) {
            float xv = xr[lane + q*32];
#pragma unroll
            for (int l = 0; l < LL; l++) acc[l] = fmaf(xv, ws[l*256 + lane + q*32], acc[l]);
        }
#pragma unroll
        for (int l = 0; l < LL; l++)
#pragma unroll
            for (int o = 16; o > 0; o >>= 1)
                acc[l] += __shfl_xor_sync(0xffffffffu, acc[l], o);

        if (lane == 0) {
            int t = m >> 6, b = m & 63;
            float* e = g_em + (size_t)b * (TT*LL) + t*LL;
#pragma unroll
            for (int l = 0; l < LL; l++) e[l] = acc[l] + bs[l];
        }
    }
}

// ---------------- 4) CRF ----------------
__global__ void __launch_bounds__(32)
crf_kernel(const int* __restrict__ word, const int* __restrict__ label,
           const float* __restrict__ start_t, const float* __restrict__ end_t,
           const float* __restrict__ trans)
{
    int b = blockIdx.x;
    int lane = threadIdx.x;
    const float* emb_ = g_em + (size_t)b * (TT*LL);

    float tr[LL];
#pragma unroll
    for (int i = 0; i < LL; i++) tr[i] = 0.f;
    if (lane < LL)
#pragma unroll
        for (int i = 0; i < LL; i++) tr[i] = trans[i*LL + lane];

    float alpha = -1e30f;
    if (lane < LL) alpha = start_t[lane] + emb_[lane];

    for (int t = 1; t < TT; t++) {
        bool mt = word[b*TT + t] > 0;
        float emj = (lane < LL) ? emb_[t*LL + lane] : 0.f;
        float vs[LL], mx = -1e30f;
#pragma unroll
        for (int i = 0; i < LL; i++) {
            float ai = __shfl_sync(0xffffffffu, alpha, i);
            vs[i] = ai + tr[i];
            mx = fmaxf(mx, vs[i]);
        }
        float s = 0.f;
#pragma unroll
        for (int i = 0; i < LL; i++) s += __expf(vs[i] - mx);
        float nxt = mx + __logf(s) + emj;
        if (lane < LL && mt) alpha = nxt;
    }

    float v = (lane < LL) ? alpha + end_t[lane] : -1e30f;
    float mx = v;
#pragma unroll
    for (int o = 16; o > 0; o >>= 1) mx = fmaxf(mx, __shfl_xor_sync(0xffffffffu, mx, o));
    float s = __expf(v - mx);
#pragma unroll
    for (int o = 16; o > 0; o >>= 1) s += __shfl_xor_sync(0xffffffffu, s, o);
    float denom = mx + __logf(s);

    float partial = 0.f;
    int cnt = 0;
    for (int t = lane; t < TT; t += 32) {
        int mt = word[b*TT + t] > 0;
        cnt += mt;
        if (t >= 1 && mt) {
            int tp = label[b*TT + t - 1];
            int tc = label[b*TT + t];
            partial += trans[tp*LL + tc] + emb_[t*LL + tc];
        }
    }
#pragma unroll
    for (int o = 16; o > 0; o >>= 1) {
        partial += __shfl_xor_sync(0xffffffffu, partial, o);
        cnt     += __shfl_xor_sync(0xffffffffu, cnt, o);
    }
    if (lane == 0) {
        int t0 = label[b*TT];
        float num = start_t[t0] + emb_[t0] + partial;
        int last = label[b*TT + cnt - 1];
        num += end_t[last];
        g_llh[b] = num - denom;
    }
}

// ---------------- 5) final reduce ----------------
__global__ void __launch_bounds__(32)
finalize(float* out)
{
    int lane = threadIdx.x;
    float v = g_llh[lane] + g_llh[lane + 32];
#pragma unroll
    for (int o = 16; o > 0; o >>= 1) v += __shfl_xor_sync(0xffffffffu, v, o);
    if (lane == 0) out[0] = -v;
}

// ---------------- host ----------------
extern "C" void kernel_launch(void* const* d_in, const int* in_sizes, int n_in,
                              void* d_out, int out_size)
{
    const int*   word    = (const int*)  d_in[0];
    const int*   label   = (const int*)  d_in[1];
    const float* emb     = (const float*)d_in[2];
    const float* w_ih_l0 = (const float*)d_in[3];
    const float* w_hh_l0 = (const float*)d_in[4];
    const float* b_ih_l0 = (const float*)d_in[5];
    const float* b_hh_l0 = (const float*)d_in[6];
    const float* w_ih_l1 = (const float*)d_in[7];
    const float* w_hh_l1 = (const float*)d_in[8];
    const float* b_ih_l1 = (const float*)d_in[9];
    const float* b_hh_l1 = (const float*)d_in[10];
    const float* w_out   = (const float*)d_in[11];
    const float* b_out   = (const float*)d_in[12];
    const float* start_t = (const float*)d_in[13];
    const float* end_t   = (const float*)d_in[14];
    const float* trans   = (const float*)d_in[15];
    float* out = (float*)d_out;

    cudaFuncSetAttribute(gemm_tf32<true>,  cudaFuncAttributeMaxDynamicSharedMemorySize, GEMM_SMEM);
    cudaFuncSetAttribute(gemm_tf32<false>, cudaFuncAttributeMaxDynamicSharedMemorySize, GEMM_SMEM);
    cudaFuncSetAttribute(lstm_scan, cudaFuncAttributeMaxDynamicSharedMemorySize, SCAN_SMEM);

    transpose_whh<<<512, 512>>>(w_hh_l0, w_hh_l1);

    gemm_tf32<true ><<<dim3(256, 8), 256, GEMM_SMEM>>>(emb, word, w_ih_l0, b_ih_l0, b_hh_l0, DD);
    lstm_scan<<<128, 512, SCAN_SMEM>>>(0);

    gemm_tf32<false><<<dim3(256, 8), 256, GEMM_SMEM>>>(nullptr, word, w_ih_l1, b_ih_l1, b_hh_l1, HD2);
    lstm_scan<<<128, 512, SCAN_SMEM>>>(1);

    emission<<<MTOK/32, 256>>>(w_out, b_out);
    crf_kernel<<<BB, 32>>>(word, label, start_t, end_t, trans);
    finalize<<<1, 32>>>(out);
}

// round 11
// speedup vs baseline: 1.3804x; 1.1374x over previous
#include <cuda_runtime.h>
#include <cstddef>
#include <cstdint>

#define BB   64
#define TT   512
#define DD   300
#define HH   128
#define G4   512
#define HD2  256
#define LL   9
#define MTOK (TT*BB)

// ---------------- device scratch ----------------
__device__ float g_xp  [ (size_t)MTOK * 1024 ];
__device__ float g_hbuf[ (size_t)MTOK * HD2  ];
__device__ float g_wt  [ 2*2*HH*G4 ];            // [layer][dir][k][g]
__device__ float g_em  [ (size_t)BB*TT*LL ];
__device__ float g_llh [ BB ];

// ---------------- intrinsics ----------------
__device__ __forceinline__ unsigned long long pack2(float lo, float hi) {
    unsigned long long r;
    asm("mov.b64 %0, {%1, %2};" : "=l"(r) : "f"(lo), "f"(hi));
    return r;
}
__device__ __forceinline__ float2 unpack2(unsigned long long v) {
    float2 f;
    asm("mov.b64 {%0, %1}, %2;" : "=f"(f.x), "=f"(f.y) : "l"(v));
    return f;
}
__device__ __forceinline__ unsigned long long ffma2(unsigned long long a,
                                                    unsigned long long b,
                                                    unsigned long long c) {
    unsigned long long d;
    asm("fma.rn.f32x2 %0, %1, %2, %3;" : "=l"(d) : "l"(a), "l"(b), "l"(c));
    return d;
}
__device__ __forceinline__ float tanh_ap(float x) {
    float y;
    asm("tanh.approx.f32 %0, %1;" : "=f"(y) : "f"(x));
    return y;
}
__device__ __forceinline__ float sig_ap(float x) {
    return fmaf(tanh_ap(0.5f * x), 0.5f, 0.5f);
}
__device__ __forceinline__ void mma_tf32(float* d, const uint32_t* a, uint32_t b0, uint32_t b1) {
    asm("mma.sync.aligned.m16n8k8.row.col.f32.tf32.tf32.f32 "
        "{%0,%1,%2,%3}, {%4,%5,%6,%7}, {%8,%9}, {%0,%1,%2,%3};"
        : "+f"(d[0]), "+f"(d[1]), "+f"(d[2]), "+f"(d[3])
        : "r"(a[0]), "r"(a[1]), "r"(a[2]), "r"(a[3]), "r"(b0), "r"(b1));
}
__device__ __forceinline__ uint32_t bf16x2_of(float lo, float hi) {
    uint32_t r;
    asm("cvt.rn.bf16x2.f32 %0, %1, %2;" : "=r"(r) : "f"(hi), "f"(lo));
    return r;
}
__device__ __forceinline__ unsigned long long bfexp(uint32_t b) {
    uint32_t lo = __byte_perm(b, 0, 0x1044);
    uint32_t hi = __byte_perm(b, 0, 0x3244);
    unsigned long long r;
    asm("mov.b64 %0, {%1, %2};" : "=l"(r) : "r"(lo), "r"(hi));
    return r;
}
__device__ __forceinline__ void cp16(uint32_t dst, const void* src, int srcbytes) {
    asm volatile("cp.async.ca.shared.global [%0], [%1], 16, %2;"
                 :: "r"(dst), "l"(src), "r"(srcbytes));
}
__device__ __forceinline__ void cp_commit() {
    asm volatile("cp.async.commit_group;");
}
template<int N>
__device__ __forceinline__ void cp_wait() {
    asm volatile("cp.async.wait_group %0;" :: "n"(N));
}

// ---------------- 0) W_hh -> k-major ----------------
__global__ void transpose_whh(const float* __restrict__ w0, const float* __restrict__ w1)
{
    int i = blockIdx.x * blockDim.x + threadIdx.x;
    if (i >= 2*2*HH*G4) return;
    int layer = i >> 17;
    int r     = i & 131071;
    int dirr  = r >> 16;
    int r2    = r & 65535;
    int k     = r2 >> 9;
    int g     = r2 & 511;
    const float* w = layer ? w1 : w0;
    g_wt[i] = w[dirr*65536 + g*HH + k];
}

// ---------------- 1) tf32 GEMM: cp.async 4-stage pipeline, k-tile 16 ----------------
#define GST 4
#define KT  16
#define GPITCH 20
#define GEMM_SMEM (GST*128*GPITCH*4*2)

template<bool GATHER>
__global__ void __launch_bounds__(256)
gemm_tf32(const float* __restrict__ Asrc, const int* __restrict__ word,
          const float* __restrict__ W, const float* __restrict__ b1,
          const float* __restrict__ b2, int K)
{
    extern __shared__ uint32_t dsm[];
    uint32_t* AsB = dsm;
    uint32_t* BsB = dsm + GST*128*GPITCH;

    __shared__ const float* arow_s[128];
    __shared__ float bias_s[128];

    const int tid = threadIdx.x;
    const int m0 = blockIdx.x * 128, n0 = blockIdx.y * 128;

    if (tid < 128) {
        int n = n0 + tid;
        bias_s[tid] = b1[n] + b2[n];
        int m = m0 + tid;
        const float* ap;
        if (GATHER) {
            int b = m & 63, t = m >> 6;
            ap = Asrc + (size_t)word[b*TT + t] * K;
        } else {
            ap = g_hbuf + (size_t)m * K;
        }
        arow_s[tid] = ap;
    }
    __syncthreads();

    const int r  = tid >> 1;
    const int kq = (tid & 1) * 4;   // wait — R7 used (tid&3)*4 with r=tid>>2
    // R7 exact loader mapping:
    const int r4  = tid >> 2;
    const int kq4 = (tid & 3) * 4;
    (void)r; (void)kq;
    const float* ar0 = arow_s[r4];
    const float* ar1 = arow_s[r4 + 64];
    const float* br0 = W + (size_t)(n0 + r4) * K;
    const float* br1 = W + (size_t)(n0 + r4 + 64) * K;

    uint32_t a_dst0 = (uint32_t)__cvta_generic_to_shared(AsB + (size_t)r4        * GPITCH + kq4);
    uint32_t a_dst1 = (uint32_t)__cvta_generic_to_shared(AsB + (size_t)(r4 + 64) * GPITCH + kq4);
    uint32_t b_dst0 = (uint32_t)__cvta_generic_to_shared(BsB + (size_t)r4        * GPITCH + kq4);
    uint32_t b_dst1 = (uint32_t)__cvta_generic_to_shared(BsB + (size_t)(r4 + 64) * GPITCH + kq4);
    const uint32_t stB = 128*GPITCH*4;

    const int warp  = tid >> 5;
    const int lane  = tid & 31;
    const int wm    = warp >> 1;
    const int wn    = warp & 1;
    const int group = lane >> 2;
    const int tig   = lane & 3;

    float acc[2][8][4];
#pragma unroll
    for (int mt = 0; mt < 2; mt++)
#pragma unroll
        for (int nt = 0; nt < 8; nt++)
#pragma unroll
            for (int q = 0; q < 4; q++) acc[mt][nt][q] = 0.f;

    const int NT = (K + KT - 1) / KT;

    auto issue_tile = [&](int kt) {
        int st = kt % GST;
        int k  = kt * KT + kq4;
        int sz = (k + 4 <= K) ? 16 : 0;
        int kc = sz ? k : 0;
        cp16(a_dst0 + st*stB, ar0 + kc, sz);
        cp16(a_dst1 + st*stB, ar1 + kc, sz);
        cp16(b_dst0 + st*stB, br0 + kc, sz);
        cp16(b_dst1 + st*stB, br1 + kc, sz);
    };

    // prime GST-1 = 3 tiles
#pragma unroll
    for (int p = 0; p < GST-1; p++) {
        if (p < NT) issue_tile(p);
        cp_commit();
    }

    for (int kt = 0; kt < NT; kt++) {
        cp_wait<GST-2>();
        __syncthreads();

        if (kt + GST-1 < NT) issue_tile(kt + GST-1);
        cp_commit();

        const uint32_t* Ast = AsB + (size_t)(kt % GST) * 128 * GPITCH;
        const uint32_t* Bst = BsB + (size_t)(kt % GST) * 128 * GPITCH;

#pragma unroll
        for (int hf = 0; hf < 2; hf++) {
            int ko = hf * 8;
            uint32_t afr[2][4];
#pragma unroll
            for (int mt = 0; mt < 2; mt++) {
                int mr = wm*32 + mt*16 + group;
                afr[mt][0] = Ast[(mr    )*GPITCH + ko + tig];
                afr[mt][1] = Ast[(mr + 8)*GPITCH + ko + tig];
                afr[mt][2] = Ast[(mr    )*GPITCH + ko + tig + 4];
                afr[mt][3] = Ast[(mr + 8)*GPITCH + ko + tig + 4];
            }
#pragma unroll
            for (int nt = 0; nt < 8; nt++) {
                int nc = wn*64 + nt*8 + group;
                uint32_t bv0 = Bst[nc*GPITCH + ko + tig];
                uint32_t bv1 = Bst[nc*GPITCH + ko + tig + 4];
                mma_tf32(acc[0][nt], afr[0], bv0, bv1);
                mma_tf32(acc[1][nt], afr[1], bv0, bv1);
            }
        }
        __syncthreads();
    }

#pragma unroll
    for (int mt = 0; mt < 2; mt++) {
        int row = m0 + wm*32 + mt*16 + group;
#pragma unroll
        for (int nt = 0; nt < 8; nt++) {
            int ncl = wn*64 + nt*8 + 2*tig;
            float bc0 = bias_s[ncl], bc1 = bias_s[ncl + 1];
            float* r0 = g_xp + (size_t)row * 1024 + n0 + ncl;
            float* r1 = r0 + (size_t)8 * 1024;
            r0[0] = acc[mt][nt][0] + bc0;  r0[1] = acc[mt][nt][1] + bc1;
            r1[0] = acc[mt][nt][2] + bc0;  r1[1] = acc[mt][nt][3] + bc1;
        }
    }
}

// ---------------- 2) LSTM scan (R7 exact: 48 f32x2 regs + 8 uint2 bf16 smem) ----------------
#define NREGP 48
#define NSMB  8
#define SCAN_SMEM (NSMB*512*8 + 128*4 + 512*4)

__global__ void __launch_bounds__(512, 1)
lstm_scan(int layer)
{
    extern __shared__ float sm[];
    uint2* wsb = (uint2*)sm;
    float* h_s = (float*)(wsb + NSMB*512);
    float* gex = h_s + 128;

    const int g   = threadIdx.x;
    const int dir = blockIdx.x >> 6;
    const int b   = blockIdx.x & 63;
    const float* pw = g_wt + (size_t)(layer*2 + dir) * 65536;

    unsigned long long wreg[NREGP];
#pragma unroll
    for (int p = 0; p < NREGP; p++)
        wreg[p] = pack2(pw[(2*p)*512 + g], pw[(2*p+1)*512 + g]);

    for (int j = 0; j < NSMB; j++) {
        int kb = 96 + 4*j;
        uint2 v;
        v.x = bf16x2_of(pw[(kb  )*512 + g], pw[(kb+1)*512 + g]);
        v.y = bf16x2_of(pw[(kb+2)*512 + g], pw[(kb+3)*512 + g]);
        wsb[j*512 + g] = v;
    }

    if (g < 128) h_s[g] = 0.f;
    float c = 0.f;
    __syncthreads();

    const float* xpp = g_xp + (size_t)(dir*512 + g);
    int t0 = dir ? (TT - 1) : 0;
    float xcur = xpp[(size_t)(t0*64 + b) * 1024];

    for (int s = 0; s < TT; s++) {
        int t = dir ? (TT - 1 - s) : s;
        int m = t*64 + b;

        float xnext = 0.f;
        if (s + 1 < TT) {
            int tn = dir ? (t - 1) : (t + 1);
            xnext = __ldg(xpp + (size_t)(tn*64 + b) * 1024);
        }

        const ulonglong2* h22 = (const ulonglong2*)h_s;
        unsigned long long acc0 = pack2(xcur, 0.f);
        unsigned long long acc1 = pack2(0.f, 0.f);
#pragma unroll
        for (int j = 0; j < NREGP/2; j++) {
            ulonglong2 hv = h22[j];
            acc0 = ffma2(hv.x, wreg[2*j],     acc0);
            acc1 = ffma2(hv.y, wreg[2*j + 1], acc1);
        }
#pragma unroll
        for (int j = 0; j < NSMB; j++) {
            ulonglong2 hv = h22[NREGP/2 + j];
            uint2 wb = wsb[j*512 + g];
            acc0 = ffma2(hv.x, bfexp(wb.x), acc0);
            acc1 = ffma2(hv.y, bfexp(wb.y), acc1);
        }
        float2 s0 = unpack2(acc0);
        float2 s1 = unpack2(acc1);
        gex[g] = (s0.x + s1.x) + (s0.y + s1.y);
        __syncthreads();

        if (g < 128) {
            float i_ = sig_ap(gex[g]);
            float f_ = sig_ap(gex[128 + g]);
            float gg = tanh_ap(gex[256 + g]);
            float o_ = sig_ap(gex[384 + g]);
            c = fmaf(f_, c, i_ * gg);
            float h = o_ * tanh_ap(c);
            h_s[g] = h;
            g_hbuf[(size_t)m * 256 + dir*128 + g] = h;
        }
        __syncthreads();
        xcur = xnext;
    }
}

// ---------------- 3) emission: 4 tokens per warp ----------------
__global__ void __launch_bounds__(256)
emission(const float* __restrict__ wout, const float* __restrict__ bout)
{
    __shared__ float ws[LL*256];
    __shared__ float bs[LL];
    int tid = threadIdx.x;
    for (int i = tid; i < LL*256; i += 256) ws[i] = wout[i];
    if (tid < LL) bs[tid] = bout[tid];
    __syncthreads();

    int w = tid >> 5, lane = tid & 31;

    for (int q4 = 0; q4 < 4; q4++) {
        int m = blockIdx.x * 32 + w * 4 + q4;
        const float* xr = g_hbuf + (size_t)m * 256;

        float acc[LL];
#pragma unroll
        for (int l = 0; l < LL; l++) acc[l] = 0.f;
#pragma unroll
        for (int q = 0; q < 8; q++) {
            float xv = xr[lane + q*32];
#pragma unroll
            for (int l = 0; l < LL; l++) acc[l] = fmaf(xv, ws[l*256 + lane + q*32], acc[l]);
        }
#pragma unroll
        for (int l = 0; l < LL; l++)
#pragma unroll
            for (int o = 16; o > 0; o >>= 1)
                acc[l] += __shfl_xor_sync(0xffffffffu, acc[l], o);

        if (lane == 0) {
            int t = m >> 6, b = m & 63;
            float* e = g_em + (size_t)b * (TT*LL) + t*LL;
#pragma unroll
            for (int l = 0; l < LL; l++) e[l] = acc[l] + bs[l];
        }
    }
}

// ---------------- 4) CRF ----------------
__global__ void __launch_bounds__(32)
crf_kernel(const int* __restrict__ word, const int* __restrict__ label,
           const float* __restrict__ start_t, const float* __restrict__ end_t,
           const float* __restrict__ trans)
{
    int b = blockIdx.x;
    int lane = threadIdx.x;
    const float* emb_ = g_em + (size_t)b * (TT*LL);

    float tr[LL];
#pragma unroll
    for (int i = 0; i < LL; i++) tr[i] = 0.f;
    if (lane < LL)
#pragma unroll
        for (int i = 0; i < LL; i++) tr[i] = trans[i*LL + lane];

    float alpha = -1e30f;
    if (lane < LL) alpha = start_t[lane] + emb_[lane];

    for (int t = 1; t < TT; t++) {
        bool mt = word[b*TT + t] > 0;
        float emj = (lane < LL) ? emb_[t*LL + lane] : 0.f;
        float vs[LL], mx = -1e30f;
#pragma unroll
        for (int i = 0; i < LL; i++) {
            float ai = __shfl_sync(0xffffffffu, alpha, i);
            vs[i] = ai + tr[i];
            mx = fmaxf(mx, vs[i]);
        }
        float s = 0.f;
#pragma unroll
        for (int i = 0; i < LL; i++) s += __expf(vs[i] - mx);
        float nxt = mx + __logf(s) + emj;
        if (lane < LL && mt) alpha = nxt;
    }

    float v = (lane < LL) ? alpha + end_t[lane] : -1e30f;
    float mx = v;
#pragma unroll
    for (int o = 16; o > 0; o >>= 1) mx = fmaxf(mx, __shfl_xor_sync(0xffffffffu, mx, o));
    float s = __expf(v - mx);
#pragma unroll
    for (int o = 16; o > 0; o >>= 1) s += __shfl_xor_sync(0xffffffffu, s, o);
    float denom = mx + __logf(s);

    float partial = 0.f;
    int cnt = 0;
    for (int t = lane; t < TT; t += 32) {
        int mt = word[b*TT + t] > 0;
        cnt += mt;
        if (t >= 1 && mt) {
            int tp = label[b*TT + t - 1];
            int tc = label[b*TT + t];
            partial += trans[tp*LL + tc] + emb_[t*LL + tc];
        }
    }
#pragma unroll
    for (int o = 16; o > 0; o >>= 1) {
        partial += __shfl_xor_sync(0xffffffffu, partial, o);
        cnt     += __shfl_xor_sync(0xffffffffu, cnt, o);
    }
    if (lane == 0) {
        int t0 = label[b*TT];
        float num = start_t[t0] + emb_[t0] + partial;
        int last = label[b*TT + cnt - 1];
        num += end_t[last];
        g_llh[b] = num - denom;
    }
}

// ---------------- 5) final reduce ----------------
__global__ void __launch_bounds__(32)
finalize(float* out)
{
    int lane = threadIdx.x;
    float v = g_llh[lane] + g_llh[lane + 32];
#pragma unroll
    for (int o = 16; o > 0; o >>= 1) v += __shfl_xor_sync(0xffffffffu, v, o);
    if (lane == 0) out[0] = -v;
}

// ---------------- host ----------------
extern "C" void kernel_launch(void* const* d_in, const int* in_sizes, int n_in,
                              void* d_out, int out_size)
{
    const int*   word    = (const int*)  d_in[0];
    const int*   label   = (const int*)  d_in[1];
    const float* emb     = (const float*)d_in[2];
    const float* w_ih_l0 = (const float*)d_in[3];
    const float* w_hh_l0 = (const float*)d_in[4];
    const float* b_ih_l0 = (const float*)d_in[5];
    const float* b_hh_l0 = (const float*)d_in[6];
    const float* w_ih_l1 = (const float*)d_in[7];
    const float* w_hh_l1 = (const float*)d_in[8];
    const float* b_ih_l1 = (const float*)d_in[9];
    const float* b_hh_l1 = (const float*)d_in[10];
    const float* w_out   = (const float*)d_in[11];
    const float* b_out   = (const float*)d_in[12];
    const float* start_t = (const float*)d_in[13];
    const float* end_t   = (const float*)d_in[14];
    const float* trans   = (const float*)d_in[15];
    float* out = (float*)d_out;

    cudaFuncSetAttribute(gemm_tf32<true>,  cudaFuncAttributeMaxDynamicSharedMemorySize, GEMM_SMEM);
    cudaFuncSetAttribute(gemm_tf32<false>, cudaFuncAttributeMaxDynamicSharedMemorySize, GEMM_SMEM);
    cudaFuncSetAttribute(lstm_scan, cudaFuncAttributeMaxDynamicSharedMemorySize, SCAN_SMEM);

    transpose_whh<<<512, 512>>>(w_hh_l0, w_hh_l1);

    gemm_tf32<true ><<<dim3(256, 8), 256, GEMM_SMEM>>>(emb, word, w_ih_l0, b_ih_l0, b_hh_l0, DD);
    lstm_scan<<<128, 512, SCAN_SMEM>>>(0);

    gemm_tf32<false><<<dim3(256, 8), 256, GEMM_SMEM>>>(nullptr, word, w_ih_l1, b_ih_l1, b_hh_l1, HD2);
    lstm_scan<<<128, 512, SCAN_SMEM>>>(1);

    emission<<<MTOK/32, 256>>>(w_out, b_out);
    crf_kernel<<<BB, 32>>>(word, label, start_t, end_t, trans);
    finalize<<<1, 32>>>(out);
}

// round 12
// speedup vs baseline: 1.3819x; 1.0011x over previous
#include <cuda_runtime.h>
#include <cstddef>
#include <cstdint>

#define BB   64
#define TT   512
#define DD   300
#define HH   128
#define G4   512
#define HD2  256
#define LL   9
#define MTOK (TT*BB)

// ---------------- device scratch ----------------
__device__ float g_xp  [ (size_t)MTOK * 1024 ];
__device__ float g_hbuf[ (size_t)MTOK * HD2  ];
__device__ float g_wt  [ 2*2*HH*G4 ];            // [layer][dir][k][g]
__device__ float g_em  [ (size_t)BB*TT*LL ];
__device__ float g_llh [ BB ];

// ---------------- intrinsics ----------------
__device__ __forceinline__ unsigned long long pack2(float lo, float hi) {
    unsigned long long r;
    asm("mov.b64 %0, {%1, %2};" : "=l"(r) : "f"(lo), "f"(hi));
    return r;
}
__device__ __forceinline__ float2 unpack2(unsigned long long v) {
    float2 f;
    asm("mov.b64 {%0, %1}, %2;" : "=f"(f.x), "=f"(f.y) : "l"(v));
    return f;
}
__device__ __forceinline__ unsigned long long ffma2(unsigned long long a,
                                                    unsigned long long b,
                                                    unsigned long long c) {
    unsigned long long d;
    asm("fma.rn.f32x2 %0, %1, %2, %3;" : "=l"(d) : "l"(a), "l"(b), "l"(c));
    return d;
}
__device__ __forceinline__ float tanh_ap(float x) {
    float y;
    asm("tanh.approx.f32 %0, %1;" : "=f"(y) : "f"(x));
    return y;
}
__device__ __forceinline__ float sig_ap(float x) {
    return fmaf(tanh_ap(0.5f * x), 0.5f, 0.5f);
}
__device__ __forceinline__ void mma_tf32(float* d, const uint32_t* a, uint32_t b0, uint32_t b1) {
    asm("mma.sync.aligned.m16n8k8.row.col.f32.tf32.tf32.f32 "
        "{%0,%1,%2,%3}, {%4,%5,%6,%7}, {%8,%9}, {%0,%1,%2,%3};"
        : "+f"(d[0]), "+f"(d[1]), "+f"(d[2]), "+f"(d[3])
        : "r"(a[0]), "r"(a[1]), "r"(a[2]), "r"(a[3]), "r"(b0), "r"(b1));
}
__device__ __forceinline__ uint32_t bf16x2_of(float lo, float hi) {
    uint32_t r;
    asm("cvt.rn.bf16x2.f32 %0, %1, %2;" : "=r"(r) : "f"(hi), "f"(lo));
    return r;
}
__device__ __forceinline__ unsigned long long bfexp(uint32_t b) {
    uint32_t lo = __byte_perm(b, 0, 0x1044);
    uint32_t hi = __byte_perm(b, 0, 0x3244);
    unsigned long long r;
    asm("mov.b64 %0, {%1, %2};" : "=l"(r) : "r"(lo), "r"(hi));
    return r;
}
__device__ __forceinline__ void cp16(uint32_t dst, const void* src, int srcbytes) {
    asm volatile("cp.async.ca.shared.global [%0], [%1], 16, %2;"
                 :: "r"(dst), "l"(src), "r"(srcbytes));
}
__device__ __forceinline__ void cp_commit() {
    asm volatile("cp.async.commit_group;");
}
template<int N>
__device__ __forceinline__ void cp_wait() {
    asm volatile("cp.async.wait_group %0;" :: "n"(N));
}

// ---------------- 0) W_hh -> k-major ----------------
__global__ void transpose_whh(const float* __restrict__ w0, const float* __restrict__ w1)
{
    int i = blockIdx.x * blockDim.x + threadIdx.x;
    if (i >= 2*2*HH*G4) return;
    int layer = i >> 17;
    int r     = i & 131071;
    int dirr  = r >> 16;
    int r2    = r & 65535;
    int k     = r2 >> 9;
    int g     = r2 & 511;
    const float* w = layer ? w1 : w0;
    g_wt[i] = w[dirr*65536 + g*HH + k];
}

// ---------------- 1) tf32 GEMM: cp.async 3-stage pipeline (R7 exact) ----------------
#define GST 3
#define KT  16
#define GPITCH 20
#define GEMM_SMEM (GST*128*GPITCH*4*2)

template<bool GATHER>
__global__ void __launch_bounds__(256)
gemm_tf32(const float* __restrict__ Asrc, const int* __restrict__ word,
          const float* __restrict__ W, const float* __restrict__ b1,
          const float* __restrict__ b2, int K)
{
    extern __shared__ uint32_t dsm[];
    uint32_t* AsB = dsm;
    uint32_t* BsB = dsm + GST*128*GPITCH;

    __shared__ const float* arow_s[128];
    __shared__ float bias_s[128];

    const int tid = threadIdx.x;
    const int m0 = blockIdx.x * 128, n0 = blockIdx.y * 128;

    if (tid < 128) {
        int n = n0 + tid;
        bias_s[tid] = b1[n] + b2[n];
        int m = m0 + tid;
        const float* ap;
        if (GATHER) {
            int b = m & 63, t = m >> 6;
            ap = Asrc + (size_t)word[b*TT + t] * K;
        } else {
            ap = g_hbuf + (size_t)m * K;
        }
        arow_s[tid] = ap;
    }
    __syncthreads();

    const int r  = tid >> 2;
    const int kq = (tid & 3) * 4;
    const float* ar0 = arow_s[r];
    const float* ar1 = arow_s[r + 64];
    const float* br0 = W + (size_t)(n0 + r) * K;
    const float* br1 = W + (size_t)(n0 + r + 64) * K;

    uint32_t a_dst0 = (uint32_t)__cvta_generic_to_shared(AsB + (size_t)r        * GPITCH + kq);
    uint32_t a_dst1 = (uint32_t)__cvta_generic_to_shared(AsB + (size_t)(r + 64) * GPITCH + kq);
    uint32_t b_dst0 = (uint32_t)__cvta_generic_to_shared(BsB + (size_t)r        * GPITCH + kq);
    uint32_t b_dst1 = (uint32_t)__cvta_generic_to_shared(BsB + (size_t)(r + 64) * GPITCH + kq);
    const uint32_t stB = 128*GPITCH*4;

    const int warp  = tid >> 5;
    const int lane  = tid & 31;
    const int wm    = warp >> 1;
    const int wn    = warp & 1;
    const int group = lane >> 2;
    const int tig   = lane & 3;

    float acc[2][8][4];
#pragma unroll
    for (int mt = 0; mt < 2; mt++)
#pragma unroll
        for (int nt = 0; nt < 8; nt++)
#pragma unroll
            for (int q = 0; q < 4; q++) acc[mt][nt][q] = 0.f;

    const int NT = (K + KT - 1) / KT;

    auto issue_tile = [&](int kt) {
        int st = kt % GST;
        int k  = kt * KT + kq;
        int sz = (k + 4 <= K) ? 16 : 0;
        int kc = sz ? k : 0;
        cp16(a_dst0 + st*stB, ar0 + kc, sz);
        cp16(a_dst1 + st*stB, ar1 + kc, sz);
        cp16(b_dst0 + st*stB, br0 + kc, sz);
        cp16(b_dst1 + st*stB, br1 + kc, sz);
    };

    issue_tile(0); cp_commit();
    if (NT > 1) { issue_tile(1); cp_commit(); }
    else cp_commit();

    for (int kt = 0; kt < NT; kt++) {
        cp_wait<1>();
        __syncthreads();

        if (kt + 2 < NT) issue_tile(kt + 2);
        cp_commit();

        const uint32_t* Ast = AsB + (size_t)(kt % GST) * 128 * GPITCH;
        const uint32_t* Bst = BsB + (size_t)(kt % GST) * 128 * GPITCH;

#pragma unroll
        for (int hf = 0; hf < 2; hf++) {
            int ko = hf * 8;
            uint32_t afr[2][4];
#pragma unroll
            for (int mt = 0; mt < 2; mt++) {
                int mr = wm*32 + mt*16 + group;
                afr[mt][0] = Ast[(mr    )*GPITCH + ko + tig];
                afr[mt][1] = Ast[(mr + 8)*GPITCH + ko + tig];
                afr[mt][2] = Ast[(mr    )*GPITCH + ko + tig + 4];
                afr[mt][3] = Ast[(mr + 8)*GPITCH + ko + tig + 4];
            }
#pragma unroll
            for (int nt = 0; nt < 8; nt++) {
                int nc = wn*64 + nt*8 + group;
                uint32_t bv0 = Bst[nc*GPITCH + ko + tig];
                uint32_t bv1 = Bst[nc*GPITCH + ko + tig + 4];
                mma_tf32(acc[0][nt], afr[0], bv0, bv1);
                mma_tf32(acc[1][nt], afr[1], bv0, bv1);
            }
        }
        __syncthreads();
    }

#pragma unroll
    for (int mt = 0; mt < 2; mt++) {
        int row = m0 + wm*32 + mt*16 + group;
#pragma unroll
        for (int nt = 0; nt < 8; nt++) {
            int ncl = wn*64 + nt*8 + 2*tig;
            float bc0 = bias_s[ncl], bc1 = bias_s[ncl + 1];
            float* r0 = g_xp + (size_t)row * 1024 + n0 + ncl;
            float* r1 = r0 + (size_t)8 * 1024;
            r0[0] = acc[mt][nt][0] + bc0;  r0[1] = acc[mt][nt][1] + bc1;
            r1[0] = acc[mt][nt][2] + bc0;  r1[1] = acc[mt][nt][3] + bc1;
        }
    }
}

// ---------------- 2) LSTM scan: R7 + distributed activations ----------------
// Thread g applies its gate's nonlinearity BEFORE storing to gex; the serial
// segment (g<128) only does the cell update (2 FMA + 1 tanh).
#define NREGP 48
#define NSMB  8
#define SCAN_SMEM (NSMB*512*8 + 128*4 + 512*4)

__global__ void __launch_bounds__(512, 1)
lstm_scan(int layer)
{
    extern __shared__ float sm[];
    uint2* wsb = (uint2*)sm;
    float* h_s = (float*)(wsb + NSMB*512);
    float* gex = h_s + 128;

    const int g   = threadIdx.x;
    const int dir = blockIdx.x >> 6;
    const int b   = blockIdx.x & 63;
    const bool is_g_gate = ((g >> 7) == 2);   // warp-uniform (128-aligned groups)
    const float* pw = g_wt + (size_t)(layer*2 + dir) * 65536;

    unsigned long long wreg[NREGP];
#pragma unroll
    for (int p = 0; p < NREGP; p++)
        wreg[p] = pack2(pw[(2*p)*512 + g], pw[(2*p+1)*512 + g]);

    for (int j = 0; j < NSMB; j++) {
        int kb = 96 + 4*j;
        uint2 v;
        v.x = bf16x2_of(pw[(kb  )*512 + g], pw[(kb+1)*512 + g]);
        v.y = bf16x2_of(pw[(kb+2)*512 + g], pw[(kb+3)*512 + g]);
        wsb[j*512 + g] = v;
    }

    if (g < 128) h_s[g] = 0.f;
    float c = 0.f;
    __syncthreads();

    const float* xpp = g_xp + (size_t)(dir*512 + g);
    int t0 = dir ? (TT - 1) : 0;
    float xcur = xpp[(size_t)(t0*64 + b) * 1024];

    for (int s = 0; s < TT; s++) {
        int t = dir ? (TT - 1 - s) : s;
        int m = t*64 + b;

        float xnext = 0.f;
        if (s + 1 < TT) {
            int tn = dir ? (t - 1) : (t + 1);
            xnext = __ldg(xpp + (size_t)(tn*64 + b) * 1024);
        }

        const ulonglong2* h22 = (const ulonglong2*)h_s;
        unsigned long long acc0 = pack2(xcur, 0.f);
        unsigned long long acc1 = pack2(0.f, 0.f);
#pragma unroll
        for (int j = 0; j < NREGP/2; j++) {
            ulonglong2 hv = h22[j];
            acc0 = ffma2(hv.x, wreg[2*j],     acc0);
            acc1 = ffma2(hv.y, wreg[2*j + 1], acc1);
        }
#pragma unroll
        for (int j = 0; j < NSMB; j++) {
            ulonglong2 hv = h22[NREGP/2 + j];
            uint2 wb = wsb[j*512 + g];
            acc0 = ffma2(hv.x, bfexp(wb.x), acc0);
            acc1 = ffma2(hv.y, bfexp(wb.y), acc1);
        }
        float2 s0 = unpack2(acc0);
        float2 s1 = unpack2(acc1);
        float accv = (s0.x + s1.x) + (s0.y + s1.y);

        // distributed activation: i/f/o -> sigmoid, g -> tanh (in parallel segment)
        gex[g] = is_g_gate ? tanh_ap(accv) : sig_ap(accv);
        __syncthreads();

        if (g < 128) {
            float i_ = gex[g];
            float f_ = gex[128 + g];
            float gg = gex[256 + g];
            float o_ = gex[384 + g];
            c = fmaf(f_, c, i_ * gg);
            float h = o_ * tanh_ap(c);
            h_s[g] = h;
            g_hbuf[(size_t)m * 256 + dir*128 + g] = h;
        }
        __syncthreads();
        xcur = xnext;
    }
}

// ---------------- 3) emission: 4 tokens per warp ----------------
__global__ void __launch_bounds__(256)
emission(const float* __restrict__ wout, const float* __restrict__ bout)
{
    __shared__ float ws[LL*256];
    __shared__ float bs[LL];
    int tid = threadIdx.x;
    for (int i = tid; i < LL*256; i += 256) ws[i] = wout[i];
    if (tid < LL) bs[tid] = bout[tid];
    __syncthreads();

    int w = tid >> 5, lane = tid & 31;

    for (int q4 = 0; q4 < 4; q4++) {
        int m = blockIdx.x * 32 + w * 4 + q4;
        const float* xr = g_hbuf + (size_t)m * 256;

        float acc[LL];
#pragma unroll
        for (int l = 0; l < LL; l++) acc[l] = 0.f;
#pragma unroll
        for (int q = 0; q < 8; q++) {
            float xv = xr[lane + q*32];
#pragma unroll
            for (int l = 0; l < LL; l++) acc[l] = fmaf(xv, ws[l*256 + lane + q*32], acc[l]);
        }
#pragma unroll
        for (int l = 0; l < LL; l++)
#pragma unroll
            for (int o = 16; o > 0; o >>= 1)
                acc[l] += __shfl_xor_sync(0xffffffffu, acc[l], o);

        if (lane == 0) {
            int t = m >> 6, b = m & 63;
            float* e = g_em + (size_t)b * (TT*LL) + t*LL;
#pragma unroll
            for (int l = 0; l < LL; l++) e[l] = acc[l] + bs[l];
        }
    }
}

// ---------------- 4) CRF ----------------
__global__ void __launch_bounds__(32)
crf_kernel(const int* __restrict__ word, const int* __restrict__ label,
           const float* __restrict__ start_t, const float* __restrict__ end_t,
           const float* __restrict__ trans)
{
    int b = blockIdx.x;
    int lane = threadIdx.x;
    const float* emb_ = g_em + (size_t)b * (TT*LL);

    float tr[LL];
#pragma unroll
    for (int i = 0; i < LL; i++) tr[i] = 0.f;
    if (lane < LL)
#pragma unroll
        for (int i = 0; i < LL; i++) tr[i] = trans[i*LL + lane];

    float alpha = -1e30f;
    if (lane < LL) alpha = start_t[lane] + emb_[lane];

    for (int t = 1; t < TT; t++) {
        bool mt = word[b*TT + t] > 0;
        float emj = (lane < LL) ? emb_[t*LL + lane] : 0.f;
        float vs[LL], mx = -1e30f;
#pragma unroll
        for (int i = 0; i < LL; i++) {
            float ai = __shfl_sync(0xffffffffu, alpha, i);
            vs[i] = ai + tr[i];
            mx = fmaxf(mx, vs[i]);
        }
        float s = 0.f;
#pragma unroll
        for (int i = 0; i < LL; i++) s += __expf(vs[i] - mx);
        float nxt = mx + __logf(s) + emj;
        if (lane < LL && mt) alpha = nxt;
    }

    float v = (lane < LL) ? alpha + end_t[lane] : -1e30f;
    float mx = v;
#pragma unroll
    for (int o = 16; o > 0; o >>= 1) mx = fmaxf(mx, __shfl_xor_sync(0xffffffffu, mx, o));
    float s = __expf(v - mx);
#pragma unroll
    for (int o = 16; o > 0; o >>= 1) s += __shfl_xor_sync(0xffffffffu, s, o);
    float denom = mx + __logf(s);

    float partial = 0.f;
    int cnt = 0;
    for (int t = lane; t < TT; t += 32) {
        int mt = word[b*TT + t] > 0;
        cnt += mt;
        if (t >= 1 && mt) {
            int tp = label[b*TT + t - 1];
            int tc = label[b*TT + t];
            partial += trans[tp*LL + tc] + emb_[t*LL + tc];
        }
    }
#pragma unroll
    for (int o = 16; o > 0; o >>= 1) {
        partial += __shfl_xor_sync(0xffffffffu, partial, o);
        cnt     += __shfl_xor_sync(0xffffffffu, cnt, o);
    }
    if (lane == 0) {
        int t0 = label[b*TT];
        float num = start_t[t0] + emb_[t0] + partial;
        int last = label[b*TT + cnt - 1];
        num += end_t[last];
        g_llh[b] = num - denom;
    }
}

// ---------------- 5) final reduce ----------------
__global__ void __launch_bounds__(32)
finalize(float* out)
{
    int lane = threadIdx.x;
    float v = g_llh[lane] + g_llh[lane + 32];
#pragma unroll
    for (int o = 16; o > 0; o >>= 1) v += __shfl_xor_sync(0xffffffffu, v, o);
    if (lane == 0) out[0] = -v;
}

// ---------------- host ----------------
extern "C" void kernel_launch(void* const* d_in, const int* in_sizes, int n_in,
                              void* d_out, int out_size)
{
    const int*   word    = (const int*)  d_in[0];
    const int*   label   = (const int*)  d_in[1];
    const float* emb     = (const float*)d_in[2];
    const float* w_ih_l0 = (const float*)d_in[3];
    const float* w_hh_l0 = (const float*)d_in[4];
    const float* b_ih_l0 = (const float*)d_in[5];
    const float* b_hh_l0 = (const float*)d_in[6];
    const float* w_ih_l1 = (const float*)d_in[7];
    const float* w_hh_l1 = (const float*)d_in[8];
    const float* b_ih_l1 = (const float*)d_in[9];
    const float* b_hh_l1 = (const float*)d_in[10];
    const float* w_out   = (const float*)d_in[11];
    const float* b_out   = (const float*)d_in[12];
    const float* start_t = (const float*)d_in[13];
    const float* end_t   = (const float*)d_in[14];
    const float* trans   = (const float*)d_in[15];
    float* out = (float*)d_out;

    cudaFuncSetAttribute(gemm_tf32<true>,  cudaFuncAttributeMaxDynamicSharedMemorySize, GEMM_SMEM);
    cudaFuncSetAttribute(gemm_tf32<false>, cudaFuncAttributeMaxDynamicSharedMemorySize, GEMM_SMEM);
    cudaFuncSetAttribute(lstm_scan, cudaFuncAttributeMaxDynamicSharedMemorySize, SCAN_SMEM);

    transpose_whh<<<512, 512>>>(w_hh_l0, w_hh_l1);

    gemm_tf32<true ><<<dim3(256, 8), 256, GEMM_SMEM>>>(emb, word, w_ih_l0, b_ih_l0, b_hh_l0, DD);
    lstm_scan<<<128, 512, SCAN_SMEM>>>(0);

    gemm_tf32<false><<<dim3(256, 8), 256, GEMM_SMEM>>>(nullptr, word, w_ih_l1, b_ih_l1, b_hh_l1, HD2);
    lstm_scan<<<128, 512, SCAN_SMEM>>>(1);

    emission<<<MTOK/32, 256>>>(w_out, b_out);
    crf_kernel<<<BB, 32>>>(word, label, start_t, end_t, trans);
    finalize<<<1, 32>>>(out);
}

// round 13
// speedup vs baseline: 1.4418x; 1.0433x over previous
#include <cuda_runtime.h>
#include <cstddef>
#include <cstdint>

#define BB   64
#define TT   512
#define DD   300
#define HH   128
#define G4   512
#define HD2  256
#define LL   9
#define MTOK (TT*BB)

// ---------------- device scratch ----------------
__device__ float g_xp  [ (size_t)MTOK * 1024 ];
__device__ float g_hbuf[ (size_t)MTOK * HD2  ];
__device__ float g_wt  [ 2*2*HH*G4 ];            // [layer][dir][k][g]
__device__ float g_em  [ (size_t)BB*TT*LL ];
__device__ float g_llh [ BB ];

// ---------------- intrinsics ----------------
__device__ __forceinline__ unsigned long long pack2(float lo, float hi) {
    unsigned long long r;
    asm("mov.b64 %0, {%1, %2};" : "=l"(r) : "f"(lo), "f"(hi));
    return r;
}
__device__ __forceinline__ float2 unpack2(unsigned long long v) {
    float2 f;
    asm("mov.b64 {%0, %1}, %2;" : "=f"(f.x), "=f"(f.y) : "l"(v));
    return f;
}
__device__ __forceinline__ unsigned long long ffma2(unsigned long long a,
                                                    unsigned long long b,
                                                    unsigned long long c) {
    unsigned long long d;
    asm("fma.rn.f32x2 %0, %1, %2, %3;" : "=l"(d) : "l"(a), "l"(b), "l"(c));
    return d;
}
__device__ __forceinline__ float tanh_ap(float x) {
    float y;
    asm("tanh.approx.f32 %0, %1;" : "=f"(y) : "f"(x));
    return y;
}
__device__ __forceinline__ float sig_ap(float x) {
    return fmaf(tanh_ap(0.5f * x), 0.5f, 0.5f);
}
__device__ __forceinline__ void mma_tf32(float* d, const uint32_t* a, uint32_t b0, uint32_t b1) {
    asm("mma.sync.aligned.m16n8k8.row.col.f32.tf32.tf32.f32 "
        "{%0,%1,%2,%3}, {%4,%5,%6,%7}, {%8,%9}, {%0,%1,%2,%3};"
        : "+f"(d[0]), "+f"(d[1]), "+f"(d[2]), "+f"(d[3])
        : "r"(a[0]), "r"(a[1]), "r"(a[2]), "r"(a[3]), "r"(b0), "r"(b1));
}
__device__ __forceinline__ uint32_t bf16x2_of(float lo, float hi) {
    uint32_t r;
    asm("cvt.rn.bf16x2.f32 %0, %1, %2;" : "=r"(r) : "f"(hi), "f"(lo));
    return r;
}
__device__ __forceinline__ unsigned long long bfexp(uint32_t b) {
    uint32_t lo = __byte_perm(b, 0, 0x1044);
    uint32_t hi = __byte_perm(b, 0, 0x3244);
    unsigned long long r;
    asm("mov.b64 %0, {%1, %2};" : "=l"(r) : "r"(lo), "r"(hi));
    return r;
}
__device__ __forceinline__ void cp16(uint32_t dst, const void* src, int srcbytes) {
    asm volatile("cp.async.ca.shared.global [%0], [%1], 16, %2;"
                 :: "r"(dst), "l"(src), "r"(srcbytes));
}
__device__ __forceinline__ void cp_commit() {
    asm volatile("cp.async.commit_group;");
}
template<int N>
__device__ __forceinline__ void cp_wait() {
    asm volatile("cp.async.wait_group %0;" :: "n"(N));
}

// ---------------- 0) W_hh -> k-major ----------------
__global__ void transpose_whh(const float* __restrict__ w0, const float* __restrict__ w1)
{
    int i = blockIdx.x * blockDim.x + threadIdx.x;
    if (i >= 2*2*HH*G4) return;
    int layer = i >> 17;
    int r     = i & 131071;
    int dirr  = r >> 16;
    int r2    = r & 65535;
    int k     = r2 >> 9;
    int g     = r2 & 511;
    const float* w = layer ? w1 : w0;
    g_wt[i] = w[dirr*65536 + g*HH + k];
}

// ---------------- 1) tf32 GEMM: cp.async 3-stage, single barrier per tile ----------------
#define GST 3
#define KT  16
#define GPITCH 20
#define GEMM_SMEM (GST*128*GPITCH*4*2)

template<bool GATHER>
__global__ void __launch_bounds__(256)
gemm_tf32(const float* __restrict__ Asrc, const int* __restrict__ word,
          const float* __restrict__ W, const float* __restrict__ b1,
          const float* __restrict__ b2, int K)
{
    extern __shared__ uint32_t dsm[];
    uint32_t* AsB = dsm;
    uint32_t* BsB = dsm + GST*128*GPITCH;

    __shared__ const float* arow_s[128];
    __shared__ float bias_s[128];

    const int tid = threadIdx.x;
    const int m0 = blockIdx.x * 128, n0 = blockIdx.y * 128;

    if (tid < 128) {
        int n = n0 + tid;
        bias_s[tid] = b1[n] + b2[n];
        int m = m0 + tid;
        const float* ap;
        if (GATHER) {
            int b = m & 63, t = m >> 6;
            ap = Asrc + (size_t)word[b*TT + t] * K;
        } else {
            ap = g_hbuf + (size_t)m * K;
        }
        arow_s[tid] = ap;
    }
    __syncthreads();

    const int r  = tid >> 2;
    const int kq = (tid & 3) * 4;
    const float* ar0 = arow_s[r];
    const float* ar1 = arow_s[r + 64];
    const float* br0 = W + (size_t)(n0 + r) * K;
    const float* br1 = W + (size_t)(n0 + r + 64) * K;

    uint32_t a_dst0 = (uint32_t)__cvta_generic_to_shared(AsB + (size_t)r        * GPITCH + kq);
    uint32_t a_dst1 = (uint32_t)__cvta_generic_to_shared(AsB + (size_t)(r + 64) * GPITCH + kq);
    uint32_t b_dst0 = (uint32_t)__cvta_generic_to_shared(BsB + (size_t)r        * GPITCH + kq);
    uint32_t b_dst1 = (uint32_t)__cvta_generic_to_shared(BsB + (size_t)(r + 64) * GPITCH + kq);
    const uint32_t stB = 128*GPITCH*4;

    const int warp  = tid >> 5;
    const int lane  = tid & 31;
    const int wm    = warp >> 1;
    const int wn    = warp & 1;
    const int group = lane >> 2;
    const int tig   = lane & 3;

    float acc[2][8][4];
#pragma unroll
    for (int mt = 0; mt < 2; mt++)
#pragma unroll
        for (int nt = 0; nt < 8; nt++)
#pragma unroll
            for (int q = 0; q < 4; q++) acc[mt][nt][q] = 0.f;

    const int NT = (K + KT - 1) / KT;

    auto issue_tile = [&](int kt) {
        int st = kt % GST;
        int k  = kt * KT + kq;
        int sz = (k + 4 <= K) ? 16 : 0;
        int kc = sz ? k : 0;
        cp16(a_dst0 + st*stB, ar0 + kc, sz);
        cp16(a_dst1 + st*stB, ar1 + kc, sz);
        cp16(b_dst0 + st*stB, br0 + kc, sz);
        cp16(b_dst1 + st*stB, br1 + kc, sz);
    };

    issue_tile(0); cp_commit();
    if (NT > 1) { issue_tile(1); cp_commit(); }
    else cp_commit();

    for (int kt = 0; kt < NT; kt++) {
        cp_wait<1>();
        __syncthreads();   // single barrier per tile: orders tile-kt visibility AND
                           // guarantees all threads finished tile-(kt-1) reads before
                           // any thread overwrites its stage below.

        if (kt + 2 < NT) issue_tile(kt + 2);
        cp_commit();

        const uint32_t* Ast = AsB + (size_t)(kt % GST) * 128 * GPITCH;
        const uint32_t* Bst = BsB + (size_t)(kt % GST) * 128 * GPITCH;

#pragma unroll
        for (int hf = 0; hf < 2; hf++) {
            int ko = hf * 8;
            uint32_t afr[2][4];
#pragma unroll
            for (int mt = 0; mt < 2; mt++) {
                int mr = wm*32 + mt*16 + group;
                afr[mt][0] = Ast[(mr    )*GPITCH + ko + tig];
                afr[mt][1] = Ast[(mr + 8)*GPITCH + ko + tig];
                afr[mt][2] = Ast[(mr    )*GPITCH + ko + tig + 4];
                afr[mt][3] = Ast[(mr + 8)*GPITCH + ko + tig + 4];
            }
#pragma unroll
            for (int nt = 0; nt < 8; nt++) {
                int nc = wn*64 + nt*8 + group;
                uint32_t bv0 = Bst[nc*GPITCH + ko + tig];
                uint32_t bv1 = Bst[nc*GPITCH + ko + tig + 4];
                mma_tf32(acc[0][nt], afr[0], bv0, bv1);
                mma_tf32(acc[1][nt], afr[1], bv0, bv1);
            }
        }
        // (bottom __syncthreads removed — proven redundant, see top-of-loop barrier)
    }

#pragma unroll
    for (int mt = 0; mt < 2; mt++) {
        int row = m0 + wm*32 + mt*16 + group;
#pragma unroll
        for (int nt = 0; nt < 8; nt++) {
            int ncl = wn*64 + nt*8 + 2*tig;
            float bc0 = bias_s[ncl], bc1 = bias_s[ncl + 1];
            float* r0 = g_xp + (size_t)row * 1024 + n0 + ncl;
            float* r1 = r0 + (size_t)8 * 1024;
            r0[0] = acc[mt][nt][0] + bc0;  r0[1] = acc[mt][nt][1] + bc1;
            r1[0] = acc[mt][nt][2] + bc0;  r1[1] = acc[mt][nt][3] + bc1;
        }
    }
}

// ---------------- 2) LSTM scan (R7 exact: 48 f32x2 regs + 8 uint2 bf16 smem) ----------------
#define NREGP 48
#define NSMB  8
#define SCAN_SMEM (NSMB*512*8 + 128*4 + 512*4)

__global__ void __launch_bounds__(512, 1)
lstm_scan(int layer)
{
    extern __shared__ float sm[];
    uint2* wsb = (uint2*)sm;
    float* h_s = (float*)(wsb + NSMB*512);
    float* gex = h_s + 128;

    const int g   = threadIdx.x;
    const int dir = blockIdx.x >> 6;
    const int b   = blockIdx.x & 63;
    const float* pw = g_wt + (size_t)(layer*2 + dir) * 65536;

    unsigned long long wreg[NREGP];
#pragma unroll
    for (int p = 0; p < NREGP; p++)
        wreg[p] = pack2(pw[(2*p)*512 + g], pw[(2*p+1)*512 + g]);

    for (int j = 0; j < NSMB; j++) {
        int kb = 96 + 4*j;
        uint2 v;
        v.x = bf16x2_of(pw[(kb  )*512 + g], pw[(kb+1)*512 + g]);
        v.y = bf16x2_of(pw[(kb+2)*512 + g], pw[(kb+3)*512 + g]);
        wsb[j*512 + g] = v;
    }

    if (g < 128) h_s[g] = 0.f;
    float c = 0.f;
    __syncthreads();

    const float* xpp = g_xp + (size_t)(dir*512 + g);
    int t0 = dir ? (TT - 1) : 0;
    float xcur = xpp[(size_t)(t0*64 + b) * 1024];

    for (int s = 0; s < TT; s++) {
        int t = dir ? (TT - 1 - s) : s;
        int m = t*64 + b;

        float xnext = 0.f;
        if (s + 1 < TT) {
            int tn = dir ? (t - 1) : (t + 1);
            xnext = __ldg(xpp + (size_t)(tn*64 + b) * 1024);
        }

        const ulonglong2* h22 = (const ulonglong2*)h_s;
        unsigned long long acc0 = pack2(xcur, 0.f);
        unsigned long long acc1 = pack2(0.f, 0.f);
#pragma unroll
        for (int j = 0; j < NREGP/2; j++) {
            ulonglong2 hv = h22[j];
            acc0 = ffma2(hv.x, wreg[2*j],     acc0);
            acc1 = ffma2(hv.y, wreg[2*j + 1], acc1);
        }
#pragma unroll
        for (int j = 0; j < NSMB; j++) {
            ulonglong2 hv = h22[NREGP/2 + j];
            uint2 wb = wsb[j*512 + g];
            acc0 = ffma2(hv.x, bfexp(wb.x), acc0);
            acc1 = ffma2(hv.y, bfexp(wb.y), acc1);
        }
        float2 s0 = unpack2(acc0);
        float2 s1 = unpack2(acc1);
        gex[g] = (s0.x + s1.x) + (s0.y + s1.y);
        __syncthreads();

        if (g < 128) {
            float i_ = sig_ap(gex[g]);
            float f_ = sig_ap(gex[128 + g]);
            float gg = tanh_ap(gex[256 + g]);
            float o_ = sig_ap(gex[384 + g]);
            c = fmaf(f_, c, i_ * gg);
            float h = o_ * tanh_ap(c);
            h_s[g] = h;
            g_hbuf[(size_t)m * 256 + dir*128 + g] = h;
        }
        __syncthreads();
        xcur = xnext;
    }
}

// ---------------- 3) emission (R7 exact: one token per warp) ----------------
__global__ void __launch_bounds__(256)
emission(const float* __restrict__ wout, const float* __restrict__ bout)
{
    __shared__ float ws[LL*256];
    __shared__ float bs[LL];
    int tid = threadIdx.x;
    for (int i = tid; i < LL*256; i += 256) ws[i] = wout[i];
    if (tid < LL) bs[tid] = bout[tid];
    __syncthreads();

    int w = tid >> 5, lane = tid & 31;
    int m = blockIdx.x * 8 + w;
    const float* xr = g_hbuf + (size_t)m * 256;

    float acc[LL];
#pragma unroll
    for (int l = 0; l < LL; l++) acc[l] = 0.f;
#pragma unroll
    for (int q = 0; q < 8; q++) {
        float xv = xr[lane + q*32];
#pragma unroll
        for (int l = 0; l < LL; l++) acc[l] = fmaf(xv, ws[l*256 + lane + q*32], acc[l]);
    }
#pragma unroll
    for (int l = 0; l < LL; l++)
#pragma unroll
        for (int o = 16; o > 0; o >>= 1)
            acc[l] += __shfl_xor_sync(0xffffffffu, acc[l], o);

    if (lane == 0) {
        int t = m >> 6, b = m & 63;
        float* e = g_em + (size_t)b * (TT*LL) + t*LL;
#pragma unroll
        for (int l = 0; l < LL; l++) e[l] = acc[l] + bs[l];
    }
}

// ---------------- 4) CRF ----------------
__global__ void __launch_bounds__(32)
crf_kernel(const int* __restrict__ word, const int* __restrict__ label,
           const float* __restrict__ start_t, const float* __restrict__ end_t,
           const float* __restrict__ trans)
{
    int b = blockIdx.x;
    int lane = threadIdx.x;
    const float* emb_ = g_em + (size_t)b * (TT*LL);

    float tr[LL];
#pragma unroll
    for (int i = 0; i < LL; i++) tr[i] = 0.f;
    if (lane < LL)
#pragma unroll
        for (int i = 0; i < LL; i++) tr[i] = trans[i*LL + lane];

    float alpha = -1e30f;
    if (lane < LL) alpha = start_t[lane] + emb_[lane];

    for (int t = 1; t < TT; t++) {
        bool mt = word[b*TT + t] > 0;
        float emj = (lane < LL) ? emb_[t*LL + lane] : 0.f;
        float vs[LL], mx = -1e30f;
#pragma unroll
        for (int i = 0; i < LL; i++) {
            float ai = __shfl_sync(0xffffffffu, alpha, i);
            vs[i] = ai + tr[i];
            mx = fmaxf(mx, vs[i]);
        }
        float s = 0.f;
#pragma unroll
        for (int i = 0; i < LL; i++) s += __expf(vs[i] - mx);
        float nxt = mx + __logf(s) + emj;
        if (lane < LL && mt) alpha = nxt;
    }

    float v = (lane < LL) ? alpha + end_t[lane] : -1e30f;
    float mx = v;
#pragma unroll
    for (int o = 16; o > 0; o >>= 1) mx = fmaxf(mx, __shfl_xor_sync(0xffffffffu, mx, o));
    float s = __expf(v - mx);
#pragma unroll
    for (int o = 16; o > 0; o >>= 1) s += __shfl_xor_sync(0xffffffffu, s, o);
    float denom = mx + __logf(s);

    float partial = 0.f;
    int cnt = 0;
    for (int t = lane; t < TT; t += 32) {
        int mt = word[b*TT + t] > 0;
        cnt += mt;
        if (t >= 1 && mt) {
            int tp = label[b*TT + t - 1];
            int tc = label[b*TT + t];
            partial += trans[tp*LL + tc] + emb_[t*LL + tc];
        }
    }
#pragma unroll
    for (int o = 16; o > 0; o >>= 1) {
        partial += __shfl_xor_sync(0xffffffffu, partial, o);
        cnt     += __shfl_xor_sync(0xffffffffu, cnt, o);
    }
    if (lane == 0) {
        int t0 = label[b*TT];
        float num = start_t[t0] + emb_[t0] + partial;
        int last = label[b*TT + cnt - 1];
        num += end_t[last];
        g_llh[b] = num - denom;
    }
}

// ---------------- 5) final reduce ----------------
__global__ void __launch_bounds__(32)
finalize(float* out)
{
    int lane = threadIdx.x;
    float v = g_llh[lane] + g_llh[lane + 32];
#pragma unroll
    for (int o = 16; o > 0; o >>= 1) v += __shfl_xor_sync(0xffffffffu, v, o);
    if (lane == 0) out[0] = -v;
}

// ---------------- host ----------------
extern "C" void kernel_launch(void* const* d_in, const int* in_sizes, int n_in,
                              void* d_out, int out_size)
{
    const int*   word    = (const int*)  d_in[0];
    const int*   label   = (const int*)  d_in[1];
    const float* emb     = (const float*)d_in[2];
    const float* w_ih_l0 = (const float*)d_in[3];
    const float* w_hh_l0 = (const float*)d_in[4];
    const float* b_ih_l0 = (const float*)d_in[5];
    const float* b_hh_l0 = (const float*)d_in[6];
    const float* w_ih_l1 = (const float*)d_in[7];
    const float* w_hh_l1 = (const float*)d_in[8];
    const float* b_ih_l1 = (const float*)d_in[9];
    const float* b_hh_l1 = (const float*)d_in[10];
    const float* w_out   = (const float*)d_in[11];
    const float* b_out   = (const float*)d_in[12];
    const float* start_t = (const float*)d_in[13];
    const float* end_t   = (const float*)d_in[14];
    const float* trans   = (const float*)d_in[15];
    float* out = (float*)d_out;

    cudaFuncSetAttribute(gemm_tf32<true>,  cudaFuncAttributeMaxDynamicSharedMemorySize, GEMM_SMEM);
    cudaFuncSetAttribute(gemm_tf32<false>, cudaFuncAttributeMaxDynamicSharedMemorySize, GEMM_SMEM);
    cudaFuncSetAttribute(lstm_scan, cudaFuncAttributeMaxDynamicSharedMemorySize, SCAN_SMEM);

    transpose_whh<<<512, 512>>>(w_hh_l0, w_hh_l1);

    gemm_tf32<true ><<<dim3(256, 8), 256, GEMM_SMEM>>>(emb, word, w_ih_l0, b_ih_l0, b_hh_l0, DD);
    lstm_scan<<<128, 512, SCAN_SMEM>>>(0);

    gemm_tf32<false><<<dim3(256, 8), 256, GEMM_SMEM>>>(nullptr, word, w_ih_l1, b_ih_l1, b_hh_l1, HD2);
    lstm_scan<<<128, 512, SCAN_SMEM>>>(1);

    emission<<<MTOK/8, 256>>>(w_out, b_out);
    crf_kernel<<<BB, 32>>>(word, label, start_t, end_t, trans);
    finalize<<<1, 32>>>(out);
}